// round 1
// baseline (speedup 1.0000x reference)
#include <cuda_runtime.h>
#include <stdint.h>

// Problem constants
#define B_SZ 8192
#define G_SZ 8
#define K_SZ 1024
#define D_SZ 64

// Tiling
#define TM 64          // rows per CTA
#define TN 64          // codes per K-chunk
#define NCHUNK (K_SZ / TN)   // 16
#define NTHREADS 256

// Output layout (all fp32, tuple concatenated):
// [0 .. 4194304)              quantized_flat (B, G*D)
// [4194304 .. 4259840)        indices (B, G) as float
// [4259840 .. 4259844)        commitment_loss, codebook_loss, entropy, perplexity
#define Q_OFF   0
#define IDX_OFF (B_SZ * G_SZ * D_SZ)                 // 4194304
#define SC_OFF  (IDX_OFF + B_SZ * G_SZ)              // 4259840

// Device scratch (no allocations allowed)
__device__ float g_c2[G_SZ * K_SZ];
__device__ int   g_hist[K_SZ];
__device__ float g_loss;

// Packed fp32x2 FMA (sm_103a FFMA2) — 2 fp32 FMAs per issue slot.
__device__ __forceinline__ unsigned long long ffma2(unsigned long long a,
                                                    unsigned long long b,
                                                    unsigned long long c) {
    unsigned long long d;
    asm("fma.rn.f32x2 %0, %1, %2, %3;" : "=l"(d) : "l"(a), "l"(b), "l"(c));
    return d;
}

// ---------------------------------------------------------------------------
// Kernel 0: zero scratch (must run every launch for determinism)
// ---------------------------------------------------------------------------
__global__ void initK() {
    int t = blockIdx.x * blockDim.x + threadIdx.x;
    if (t < K_SZ) g_hist[t] = 0;
    if (t == 0) g_loss = 0.0f;
}

// ---------------------------------------------------------------------------
// Kernel 1: c2[g*K + k] = sum_d codebook[g][k][d]^2   (warp per code)
// ---------------------------------------------------------------------------
__global__ void c2K(const float* __restrict__ cb) {
    int code = blockIdx.x * 8 + (threadIdx.x >> 5);   // 8 warps per block
    int lane = threadIdx.x & 31;
    const float* p = cb + (size_t)code * D_SZ;
    float a = p[lane], b = p[lane + 32];
    float s = a * a + b * b;
    #pragma unroll
    for (int o = 16; o; o >>= 1) s += __shfl_xor_sync(0xFFFFFFFFu, s, o);
    if (lane == 0) g_c2[code] = s;
}

// ---------------------------------------------------------------------------
// Kernel 2: fused distance GEMM + argmin + gather + quantized write
//           + commitment-loss partial + usage histogram
// ---------------------------------------------------------------------------
__global__ __launch_bounds__(NTHREADS, 2)
void mainK(const float* __restrict__ z, const float* __restrict__ cb,
           float* __restrict__ out, int out_size) {
    __shared__ float zs[TM][D_SZ];        // 16 KB, natural layout (reads are broadcast)
    __shared__ float cts[TN * D_SZ];      // 16 KB, XOR-swizzled 16B chunks; reused for argmin reduce
    __shared__ float c2s[TN];
    __shared__ int   bestkS[TM];
    __shared__ float wsum[NTHREADS / 32];

    const int tid = threadIdx.x;
    const int tx = tid & 15;              // code dimension (16 lanes)
    const int ty = tid >> 4;              // row dimension (16 lanes)
    const int b0 = blockIdx.x * TM;
    const int g  = blockIdx.y;
    const float* __restrict__ cbg = cb + (size_t)g * K_SZ * D_SZ;

    // --- load z tile (coalesced float4) ---
    #pragma unroll
    for (int t = 0; t < (TM * D_SZ / 4) / NTHREADS; t++) {   // 4 iters
        int idx = tid + t * NTHREADS;
        int r = idx >> 4, dq = idx & 15;
        float4 v = *(const float4*)(z + (size_t)(b0 + r) * (G_SZ * D_SZ) + g * D_SZ + dq * 4);
        *(float4*)&zs[r][dq * 4] = v;
    }

    float minv[4];
    int   mink[4];
    #pragma unroll
    for (int i = 0; i < 4; i++) { minv[i] = 3.4e38f; mink[i] = 0; }

    // --- prefetch chunk 0 ---
    float4 pf[4];
    float c2pf = 0.0f;
    {
        int c = tid >> 4, dq = tid & 15;   // 16 codes per 256-thread pass? -> need 4 passes worth: do per-thread 4 loads
        #pragma unroll
        for (int t = 0; t < 4; t++) {
            int idx = tid + t * NTHREADS;
            int cc = idx >> 4, dqq = idx & 15;
            pf[t] = *(const float4*)(cbg + (size_t)cc * D_SZ + dqq * 4);
        }
        (void)c; (void)dq;
        if (tid < TN) c2pf = g_c2[g * K_SZ + tid];
    }

    for (int kc = 0; kc < NCHUNK; kc++) {
        __syncthreads();   // previous compute / reduce done before overwriting cts
        // store prefetched chunk, swizzled: chunk dq goes to slot dq ^ ((code>>2)&7)
        #pragma unroll
        for (int t = 0; t < 4; t++) {
            int idx = tid + t * NTHREADS;
            int cc = idx >> 4, dqq = idx & 15;
            int sw = dqq ^ ((cc >> 2) & 7);
            *(float4*)&cts[cc * D_SZ + sw * 4] = pf[t];
        }
        if (tid < TN) c2s[tid] = c2pf;
        __syncthreads();

        // prefetch next chunk (latency hidden under FFMA loop)
        if (kc + 1 < NCHUNK) {
            #pragma unroll
            for (int t = 0; t < 4; t++) {
                int idx = tid + t * NTHREADS;
                int cc = idx >> 4, dqq = idx & 15;
                pf[t] = *(const float4*)(cbg + (size_t)((kc + 1) * TN + cc) * D_SZ + dqq * 4);
            }
            if (tid < TN) c2pf = g_c2[g * K_SZ + (kc + 1) * TN + tid];
        }

        // --- 4x4 register tile, pairs packed along D ---
        unsigned long long acc[4][4];
        #pragma unroll
        for (int i = 0; i < 4; i++)
            #pragma unroll
            for (int j = 0; j < 4; j++) acc[i][j] = 0ull;

        #pragma unroll
        for (int dc = 0; dc < 16; dc++) {           // 4 D-values per step
            ulonglong2 a[4], b[4];
            #pragma unroll
            for (int i = 0; i < 4; i++)
                a[i] = *(const ulonglong2*)&zs[ty * 4 + i][dc * 4];
            #pragma unroll
            for (int j = 0; j < 4; j++) {
                int code = tx * 4 + j;
                int sw = dc ^ ((code >> 2) & 7);    // code>>2 == tx
                b[j] = *(const ulonglong2*)&cts[code * D_SZ + sw * 4];
            }
            #pragma unroll
            for (int i = 0; i < 4; i++)
                #pragma unroll
                for (int j = 0; j < 4; j++) {
                    acc[i][j] = ffma2(a[i].x, b[j].x, acc[i][j]);
                    acc[i][j] = ffma2(a[i].y, b[j].y, acc[i][j]);
                }
        }

        // distance (z2 dropped: row-constant, argmin-invariant) + running min
        #pragma unroll
        for (int j = 0; j < 4; j++) {
            float c2v = c2s[tx * 4 + j];
            int k = kc * TN + tx * 4 + j;
            #pragma unroll
            for (int i = 0; i < 4; i++) {
                float lo = __uint_as_float((unsigned)(acc[i][j] & 0xFFFFFFFFu));
                float hi = __uint_as_float((unsigned)(acc[i][j] >> 32));
                float dist = c2v - 2.0f * (lo + hi);
                if (dist < minv[i]) { minv[i] = dist; mink[i] = k; }
            }
        }
    }

    // --- cross-tx argmin reduction (reuse cts) ---
    __syncthreads();
    float* redv = cts;                       // TM*16 floats
    int*   redi = (int*)(cts + TM * 16);     // TM*16 ints
    #pragma unroll
    for (int i = 0; i < 4; i++) {
        int r = ty * 4 + i;
        redv[r * 16 + tx] = minv[i];
        redi[r * 16 + tx] = mink[i];
    }
    __syncthreads();

    if (tid < TM) {
        float bv = redv[tid * 16];
        int   bk = redi[tid * 16];
        #pragma unroll
        for (int t = 1; t < 16; t++) {
            float v = redv[tid * 16 + t];
            int   k = redi[tid * 16 + t];
            if (v < bv || (v == bv && k < bk)) { bv = v; bk = k; }  // first-index ties
        }
        bestkS[tid] = bk;
        if (out_size >= IDX_OFF + B_SZ * G_SZ)
            out[IDX_OFF + (size_t)(b0 + tid) * G_SZ + g] = (float)bk;
        atomicAdd(&g_hist[bk], 1);
    }
    __syncthreads();

    // --- gather codebook row -> quantized output + commitment loss partial ---
    float lsum = 0.0f;
    {
        int r = tid >> 2;            // 64 rows x 4 threads
        int q = tid & 3;             // 16 floats each
        int bk = bestkS[r];
        const float* cp = cbg + (size_t)bk * D_SZ + q * 16;
        float* op = out + Q_OFF + (size_t)(b0 + r) * (G_SZ * D_SZ) + g * D_SZ + q * 16;
        #pragma unroll
        for (int u = 0; u < 4; u++) {
            float4 cv = *(const float4*)(cp + u * 4);
            float4 zv = *(const float4*)&zs[r][q * 16 + u * 4];
            float dx = zv.x - cv.x, dy = zv.y - cv.y;
            float dz = zv.z - cv.z, dw = zv.w - cv.w;
            lsum += dx * dx + dy * dy + dz * dz + dw * dw;
            *(float4*)(op + u * 4) = cv;
        }
    }
    #pragma unroll
    for (int o = 16; o; o >>= 1) lsum += __shfl_xor_sync(0xFFFFFFFFu, lsum, o);
    if ((tid & 31) == 0) wsum[tid >> 5] = lsum;
    __syncthreads();
    if (tid == 0) {
        float s = 0.0f;
        #pragma unroll
        for (int w = 0; w < NTHREADS / 32; w++) s += wsum[w];
        atomicAdd(&g_loss, s);
    }
}

// ---------------------------------------------------------------------------
// Kernel 3: entropy / perplexity / loss scalars
// ---------------------------------------------------------------------------
__global__ void finalK(float* __restrict__ out, int out_size) {
    __shared__ float sh[8];
    int t = threadIdx.x;
    float e = 0.0f;
    for (int k = t; k < K_SZ; k += 256) {
        float u = (float)g_hist[k] * (1.0f / (float)(B_SZ * G_SZ));
        e -= u * logf(u + 1e-10f);
    }
    #pragma unroll
    for (int o = 16; o; o >>= 1) e += __shfl_xor_sync(0xFFFFFFFFu, e, o);
    if ((t & 31) == 0) sh[t >> 5] = e;
    __syncthreads();
    if (t == 0) {
        float s = 0.0f;
        #pragma unroll
        for (int w = 0; w < 8; w++) s += sh[w];
        if (out_size >= SC_OFF + 4) {
            out[SC_OFF + 0] = g_loss / (float)(B_SZ * G_SZ * D_SZ);
            out[SC_OFF + 1] = 0.0f;          // codebook_loss
            out[SC_OFF + 2] = s;             // entropy
            out[SC_OFF + 3] = expf(s);       // perplexity
        }
    }
}

// ---------------------------------------------------------------------------
extern "C" void kernel_launch(void* const* d_in, const int* in_sizes, int n_in,
                              void* d_out, int out_size) {
    const float* z  = (const float*)d_in[0];   // (B, G*D) fp32
    const float* cb = (const float*)d_in[1];   // (G, K, D) fp32
    float* out = (float*)d_out;

    initK<<<4, 256>>>();
    c2K<<<(G_SZ * K_SZ) / 8, 256>>>(cb);
    dim3 grid(B_SZ / TM, G_SZ);
    mainK<<<grid, NTHREADS>>>(z, cb, out, out_size);
    finalK<<<1, 256>>>(out, out_size);
}

// round 8
// speedup vs baseline: 1.0417x; 1.0417x over previous
#include <cuda_runtime.h>
#include <stdint.h>

// Problem constants
#define B_SZ 8192
#define G_SZ 8
#define K_SZ 1024
#define D_SZ 64

// Tiling
#define TM 64                 // rows per CTA
#define TN 64                 // codes per K-chunk
#define NCHUNK (K_SZ / TN)    // 16
#define NTHREADS 256
#define ROWPAD 68             // padded row stride (floats); 16B-aligned rows

// Dynamic smem layout (floats): zs[TM*ROWPAD] | cts0[TN*ROWPAD] | cts1[TN*ROWPAD]
#define ZS_F    (TM * ROWPAD)
#define CT_F    (TN * ROWPAD)
#define SMEM_BYTES ((ZS_F + 2 * CT_F) * 4)

// Output layout (fp32, tuple concatenated):
#define Q_OFF   0
#define IDX_OFF (B_SZ * G_SZ * D_SZ)                 // 4194304
#define SC_OFF  (IDX_OFF + B_SZ * G_SZ)              // 4259840

// Device scratch (zero-initialized at load; finalK re-zeros after use each call)
__device__ int   g_hist[K_SZ];
__device__ float g_loss;

// Packed fp32x2 FMA (sm_103a FFMA2) — 2 fp32 FMAs per issue slot.
__device__ __forceinline__ unsigned long long ffma2(unsigned long long a,
                                                    unsigned long long b,
                                                    unsigned long long c) {
    unsigned long long d;
    asm("fma.rn.f32x2 %0, %1, %2, %3;" : "=l"(d) : "l"(a), "l"(b), "l"(c));
    return d;
}

// ---------------------------------------------------------------------------
// Kernel 1: fused c2 + distance GEMM + argmin + gather + quantized write
//           + commitment-loss partial + usage histogram
// ---------------------------------------------------------------------------
__global__ __launch_bounds__(NTHREADS, 2)
void mainK(const float* __restrict__ z, const float* __restrict__ cb,
           float* __restrict__ out) {
    extern __shared__ float smem[];
    float* zs   = smem;                    // TM rows, ROWPAD stride
    float* cts0 = smem + ZS_F;
    float* cts1 = smem + ZS_F + CT_F;

    __shared__ float c2s[2][TN];
    __shared__ int   bestkS[TM];
    __shared__ float wsum[NTHREADS / 32];

    const int tid = threadIdx.x;
    const int tx = tid & 15;              // code dimension (stride-1 codes)
    const int ty = tid >> 4;              // row dimension
    const int b0 = blockIdx.x * TM;
    const int g  = blockIdx.y;
    const float* __restrict__ cbg = cb + (size_t)g * K_SZ * D_SZ;

    const int ld_q  = tid & 15;           // quad index within row
    const int ld_c0 = tid >> 4;           // base row/code (t adds 16)

    // --- load z tile (coalesced float4, padded store) ---
    #pragma unroll
    for (int t = 0; t < 4; t++) {
        int r = ld_c0 + t * 16;
        float4 v = *(const float4*)(z + (size_t)(b0 + r) * (G_SZ * D_SZ) + g * D_SZ + ld_q * 4);
        *(float4*)&zs[r * ROWPAD + ld_q * 4] = v;
    }

    float minv[4];
    int   mink[4];
    #pragma unroll
    for (int i = 0; i < 4; i++) { minv[i] = 3.4e38f; mink[i] = 0; }

    float4 pf[4];

    #define LDG_CHUNK(kc_) do {                                                   \
        _Pragma("unroll")                                                         \
        for (int t = 0; t < 4; t++) {                                             \
            int cc = ld_c0 + t * 16;                                              \
            pf[t] = *(const float4*)(cbg + (size_t)((kc_) * TN + cc) * D_SZ + ld_q * 4); \
        } } while (0)

    // c2 from pf via intra-halfwarp shuffle over the 16 ld_q lanes
    #define C2_FROM_PF(buf_) do {                                                 \
        _Pragma("unroll")                                                         \
        for (int t = 0; t < 4; t++) {                                             \
            float4 v = pf[t];                                                     \
            float s = v.x * v.x + v.y * v.y + v.z * v.z + v.w * v.w;              \
            s += __shfl_xor_sync(0xFFFFFFFFu, s, 1);                              \
            s += __shfl_xor_sync(0xFFFFFFFFu, s, 2);                              \
            s += __shfl_xor_sync(0xFFFFFFFFu, s, 4);                              \
            s += __shfl_xor_sync(0xFFFFFFFFu, s, 8);                              \
            if (ld_q == 0) c2s[buf_][ld_c0 + t * 16] = s;                         \
        } } while (0)

    #define STORE_CHUNK(dst_) do {                                                \
        _Pragma("unroll")                                                         \
        for (int t = 0; t < 4; t++) {                                             \
            int cc = ld_c0 + t * 16;                                              \
            *(float4*)&(dst_)[cc * ROWPAD + ld_q * 4] = pf[t];                    \
        } } while (0)

    // one chunk of the distance GEMM: 4x4 register tile, FFMA2 pairs along D
    #define COMPUTE_CHUNK(cbuf_, cbi_, kc_) do {                                  \
        unsigned long long acc[4][4];                                             \
        _Pragma("unroll")                                                         \
        for (int i = 0; i < 4; i++)                                               \
            _Pragma("unroll")                                                     \
            for (int j = 0; j < 4; j++) acc[i][j] = 0ull;                         \
        _Pragma("unroll")                                                         \
        for (int dc = 0; dc < 16; dc++) {                                         \
            ulonglong2 a[4], b[4];                                                \
            _Pragma("unroll")                                                     \
            for (int i = 0; i < 4; i++)                                           \
                a[i] = *(const ulonglong2*)&zs[(ty * 4 + i) * ROWPAD + dc * 4];   \
            _Pragma("unroll")                                                     \
            for (int j = 0; j < 4; j++)                                           \
                b[j] = *(const ulonglong2*)&(cbuf_)[(j * 16 + tx) * ROWPAD + dc * 4]; \
            _Pragma("unroll")                                                     \
            for (int i = 0; i < 4; i++)                                           \
                _Pragma("unroll")                                                 \
                for (int j = 0; j < 4; j++) {                                     \
                    acc[i][j] = ffma2(a[i].x, b[j].x, acc[i][j]);                 \
                    acc[i][j] = ffma2(a[i].y, b[j].y, acc[i][j]);                 \
                }                                                                 \
        }                                                                         \
        _Pragma("unroll")                                                         \
        for (int j = 0; j < 4; j++) {                                             \
            float c2v = c2s[cbi_][j * 16 + tx];                                   \
            int k = (kc_) * TN + j * 16 + tx;                                     \
            _Pragma("unroll")                                                     \
            for (int i = 0; i < 4; i++) {                                         \
                float lo = __uint_as_float((unsigned)(acc[i][j] & 0xFFFFFFFFu));  \
                float hi = __uint_as_float((unsigned)(acc[i][j] >> 32));          \
                float dist = c2v - 2.0f * (lo + hi);                              \
                if (dist < minv[i]) { minv[i] = dist; mink[i] = k; }              \
            }                                                                     \
        } } while (0)

    // prologue: chunk 0 into buffer 0
    LDG_CHUNK(0);
    C2_FROM_PF(0);
    STORE_CHUNK(cts0);
    __syncthreads();

    // unrolled x2 so buffer selection is compile-time (immediate-offset LDS)
    #pragma unroll 1
    for (int kc = 0; kc < NCHUNK; kc += 2) {
        // --- even chunk: compute cts0, fill cts1 ---
        LDG_CHUNK(kc + 1);
        COMPUTE_CHUNK(cts0, 0, kc);
        C2_FROM_PF(1);
        STORE_CHUNK(cts1);
        __syncthreads();

        // --- odd chunk: compute cts1, fill cts0 ---
        if (kc + 2 < NCHUNK) LDG_CHUNK(kc + 2);
        COMPUTE_CHUNK(cts1, 1, kc + 1);
        if (kc + 2 < NCHUNK) {
            C2_FROM_PF(0);
            STORE_CHUNK(cts0);
        }
        __syncthreads();
    }

    // --- cross-tx argmin reduction (alias dead cts buffers) ---
    float* redv = cts0;                    // TM*16 floats
    int*   redi = (int*)cts1;              // TM*16 ints
    #pragma unroll
    for (int i = 0; i < 4; i++) {
        int r = ty * 4 + i;
        redv[r * 16 + tx] = minv[i];
        redi[r * 16 + tx] = mink[i];
    }
    __syncthreads();

    if (tid < TM) {
        float bv = redv[tid * 16];
        int   bk = redi[tid * 16];
        #pragma unroll
        for (int t = 1; t < 16; t++) {
            float v = redv[tid * 16 + t];
            int   k = redi[tid * 16 + t];
            if (v < bv || (v == bv && k < bk)) { bv = v; bk = k; }  // first-index ties
        }
        bestkS[tid] = bk;
        out[IDX_OFF + (size_t)(b0 + tid) * G_SZ + g] = (float)bk;
        atomicAdd(&g_hist[bk], 1);
    }
    __syncthreads();

    // --- gather codebook row -> quantized output + commitment loss partial ---
    float lsum = 0.0f;
    {
        int r = tid >> 2;            // 64 rows x 4 threads
        int q = tid & 3;             // 16 floats each
        int bk = bestkS[r];
        const float* cp = cbg + (size_t)bk * D_SZ + q * 16;
        float* op = out + Q_OFF + (size_t)(b0 + r) * (G_SZ * D_SZ) + g * D_SZ + q * 16;
        #pragma unroll
        for (int u = 0; u < 4; u++) {
            float4 cv = *(const float4*)(cp + u * 4);
            float4 zv = *(const float4*)&zs[r * ROWPAD + q * 16 + u * 4];
            float dx = zv.x - cv.x, dy = zv.y - cv.y;
            float dz = zv.z - cv.z, dw = zv.w - cv.w;
            lsum += dx * dx + dy * dy + dz * dz + dw * dw;
            *(float4*)(op + u * 4) = cv;
        }
    }
    #pragma unroll
    for (int o = 16; o; o >>= 1) lsum += __shfl_xor_sync(0xFFFFFFFFu, lsum, o);
    if ((tid & 31) == 0) wsum[tid >> 5] = lsum;
    __syncthreads();
    if (tid == 0) {
        float s = 0.0f;
        #pragma unroll
        for (int w = 0; w < NTHREADS / 32; w++) s += wsum[w];
        atomicAdd(&g_loss, s);
    }
}

// ---------------------------------------------------------------------------
// Kernel 2: entropy / perplexity / loss scalars, then re-zero scratch
// ---------------------------------------------------------------------------
__global__ void finalK(float* __restrict__ out) {
    __shared__ float sh[8];
    int t = threadIdx.x;
    float e = 0.0f;
    for (int k = t; k < K_SZ; k += 256) {
        float u = (float)g_hist[k] * (1.0f / (float)(B_SZ * G_SZ));
        e -= u * logf(u + 1e-10f);
    }
    #pragma unroll
    for (int o = 16; o; o >>= 1) e += __shfl_xor_sync(0xFFFFFFFFu, e, o);
    if ((t & 31) == 0) sh[t >> 5] = e;
    __syncthreads();
    if (t == 0) {
        float s = 0.0f;
        #pragma unroll
        for (int w = 0; w < 8; w++) s += sh[w];
        out[SC_OFF + 0] = g_loss / (float)(B_SZ * G_SZ * D_SZ);
        out[SC_OFF + 1] = 0.0f;          // codebook_loss
        out[SC_OFF + 2] = s;             // entropy
        out[SC_OFF + 3] = expf(s);       // perplexity
        g_loss = 0.0f;                   // re-arm scratch for next replay
    }
    __syncthreads();
    for (int k = t; k < K_SZ; k += 256) g_hist[k] = 0;
}

// ---------------------------------------------------------------------------
extern "C" void kernel_launch(void* const* d_in, const int* in_sizes, int n_in,
                              void* d_out, int out_size) {
    const float* z  = (const float*)d_in[0];   // (B, G*D) fp32
    const float* cb = (const float*)d_in[1];   // (G, K, D) fp32
    float* out = (float*)d_out;

    // Opt-in to >48KB dynamic smem (idempotent attribute call, not a stream op)
    cudaFuncSetAttribute(mainK, cudaFuncAttributeMaxDynamicSharedMemorySize, SMEM_BYTES);

    dim3 grid(B_SZ / TM, G_SZ);
    mainK<<<grid, NTHREADS, SMEM_BYTES>>>(z, cb, out);
    finalK<<<1, 256>>>(out);
}